// round 4
// baseline (speedup 1.0000x reference)
#include <cuda_runtime.h>
#include <math.h>
#include <stdint.h>

// Problem dims
constexpr int BB = 64;
constexpr int TT = 32;
constexpr int SS = 31;     // scan steps (T-1)
constexpr int VV = 10000;
constexpr int EE = 300;
constexpr int HH = 256;
constexpr int FF = 4096;
constexpr int GG = 1024;   // 4*H
constexpr int KIN = HH + EE;   // 556
constexpr int KAP = 576;       // KIN padded to 16
constexpr int MROWS = SS * BB; // 1984
constexpr int RB = 8;          // recurrence cluster CTAs

// -------------------- device scratch (static, no allocs) --------------------
__device__ float d_Xp[BB * HH];
__device__ float d_xpart[16 * BB * HH];
__device__ float d_Acat[MROWS * KAP];      // [Xp | emb | 0], tf32-rounded
__device__ float d_bias2[GG];              // b_ih + b_hh
__device__ float d_gpre[MROWS * GG];       // precomputed gate inputs
__device__ float d_Hall[MROWS * HH];       // h history, tf32-rounded (fc2 A)
__device__ float d_logits[MROWS * VV];
__device__ int   d_labels[TT * BB];

// -------------------- helpers ------------------------------------------------
__device__ __forceinline__ void cp16(void* smem_dst, const void* gsrc, bool pred) {
    uint32_t saddr = (uint32_t)__cvta_generic_to_shared(smem_dst);
    int sz = pred ? 16 : 0;
    asm volatile("cp.async.cg.shared.global [%0], [%1], 16, %2;\n"
                 :: "r"(saddr), "l"(gsrc), "r"(sz) : "memory");
}
__device__ __forceinline__ uint32_t f2tf(float x) {
    uint32_t r;
    asm("cvt.rna.tf32.f32 %0, %1;" : "=r"(r) : "f"(x));
    return r;
}
__device__ __forceinline__ void mma_tf32(float* d, const uint32_t* a, const uint32_t* b) {
    asm volatile(
        "mma.sync.aligned.m16n8k8.row.col.f32.tf32.tf32.f32 "
        "{%0,%1,%2,%3}, {%4,%5,%6,%7}, {%8,%9}, {%0,%1,%2,%3};"
        : "+f"(d[0]), "+f"(d[1]), "+f"(d[2]), "+f"(d[3])
        : "r"(a[0]), "r"(a[1]), "r"(a[2]), "r"(a[3]), "r"(b[0]), "r"(b[1]));
}

// -------------------- fused prep: label decode + combined bias ---------------
__global__ void k_prep(const int* __restrict__ lab,
                       const float* __restrict__ bih,
                       const float* __restrict__ bhh) {
    __shared__ int is64;
    if (threadIdx.x == 0) {
        int f = 1;
        for (int i = 1; i < 64 && f; i += 2)
            if (lab[i] != 0) f = 0;
        is64 = f;
    }
    __syncthreads();
    for (int i = threadIdx.x; i < TT * BB; i += blockDim.x)
        d_labels[i] = is64 ? (int)(((const long long*)lab)[i]) : lab[i];
    for (int i = threadIdx.x; i < GG; i += blockDim.x)
        d_bias2[i] = bih[i] + bhh[i];
}

// -------------------- fc1: Xp = X @ fc1_w.T + b (split-K SIMT) ---------------
__global__ void __launch_bounds__(256) k_fc1(const float* __restrict__ X,
                                             const float* __restrict__ W) {
    const int h0 = blockIdx.x * 32;
    const int kb = blockIdx.y;
    const int kbase = kb * 256;
    const int tid = threadIdx.x;
    __shared__ __align__(16) float Xs[32][68];
    __shared__ float Wsh[32][33];
    float acc[4][2];
#pragma unroll
    for (int q = 0; q < 4; q++) { acc[q][0] = 0.f; acc[q][1] = 0.f; }
    const int tb = (tid & 15) * 4;
    const int th = (tid >> 4) * 2;

    for (int t = 0; t < 8; t++) {
        int k0 = kbase + t * 32;
#pragma unroll
        for (int i = 0; i < 8; i++) {
            int idx = tid + i * 256;
            int b = idx >> 5, kk = idx & 31;
            Xs[kk][b] = X[(size_t)b * FF + k0 + kk];
        }
#pragma unroll
        for (int i = 0; i < 4; i++) {
            int idx = tid + i * 256;
            int hh = idx >> 5, kk = idx & 31;
            Wsh[kk][hh] = W[(size_t)(h0 + hh) * FF + k0 + kk];
        }
        __syncthreads();
#pragma unroll
        for (int kk = 0; kk < 32; kk++) {
            float4 x4 = *(const float4*)&Xs[kk][tb];
            float w0 = Wsh[kk][th], w1 = Wsh[kk][th + 1];
            acc[0][0] += x4.x * w0; acc[0][1] += x4.x * w1;
            acc[1][0] += x4.y * w0; acc[1][1] += x4.y * w1;
            acc[2][0] += x4.z * w0; acc[2][1] += x4.z * w1;
            acc[3][0] += x4.w * w0; acc[3][1] += x4.w * w1;
        }
        __syncthreads();
    }
#pragma unroll
    for (int q = 0; q < 4; q++)
#pragma unroll
        for (int j = 0; j < 2; j++)
            d_xpart[kb * (BB * HH) + (tb + q) * HH + h0 + th + j] = acc[q][j];
}

__global__ void k_fc1red(const float* __restrict__ fc1_b) {
    int i4 = blockIdx.x * 256 + threadIdx.x;     // float4 index, 4096 total
    if (i4 < BB * HH / 4) {
        const float4* bp = (const float4*)fc1_b;
        float4 s = bp[i4 & 63];
#pragma unroll
        for (int kb = 0; kb < 16; kb++) {
            float4 p = ((const float4*)(d_xpart + kb * BB * HH))[i4];
            s.x += p.x; s.y += p.y; s.z += p.z; s.w += p.w;
        }
        ((float4*)d_Xp)[i4] = s;
    }
}

// -------------------- build A = [Xp | emb | 0] (tf32-rounded, float4) --------
constexpr int AC4 = KAP / 4;   // 144 float4 per row
__global__ void k_buildA(const float* __restrict__ emb_table) {
    int idx = blockIdx.x * 256 + threadIdx.x;
    if (idx >= MROWS * AC4) return;
    int r = idx / AC4, c = idx - r * AC4;
    int s = r >> 6, b = r & 63;
    float4 v;
    if (c < 64) {
        v = ((const float4*)d_Xp)[b * 64 + c];
    } else if (c < 139) {
        int tok = (s == 0) ? 1 : d_labels[s * BB + b];   // START_ID = 1
        v = *(const float4*)(emb_table + (size_t)tok * EE + (c - 64) * 4);
    } else {
        v = make_float4(0.f, 0.f, 0.f, 0.f);
    }
    v.x = __uint_as_float(f2tf(v.x));
    v.y = __uint_as_float(f2tf(v.y));
    v.z = __uint_as_float(f2tf(v.z));
    v.w = __uint_as_float(f2tf(v.w));
    ((float4*)d_Acat)[idx] = v;
}

// -------------------- generic tf32 GEMM ---------------------------------------
// C[M,N] = A[M,K] @ B[N,K]^T + bias[N]; 128x128 tile, BK=16, 8 warps.
// Raw fp32 operands are truncated to tf32 by the mma (fine at our error budget).
__global__ void __launch_bounds__(256) k_tcgemm(
    const float* __restrict__ A, int lda,
    const float* __restrict__ B, int ldb,
    const float* __restrict__ bias,
    float* __restrict__ C, int ldc,
    int M, int N, int K, int Ka, int Kb)
{
    __shared__ float As[2][128][20];
    __shared__ float Bs[2][128][20];

    const int tid = threadIdx.x;
    const int lane = tid & 31;
    const int warpId = tid >> 5;
    const int warpM = warpId & 3;
    const int warpN = warpId >> 2;
    const int g = lane >> 2;
    const int t = lane & 3;

    const int ncol = blockIdx.x * 128;
    const int mrow = blockIdx.y * 128;

    float acc[2][8][4];
#pragma unroll
    for (int mt = 0; mt < 2; mt++)
#pragma unroll
        for (int nt = 0; nt < 8; nt++)
#pragma unroll
            for (int q = 0; q < 4; q++) acc[mt][nt][q] = 0.f;

    const int NT = K >> 4;

    auto load_tile = [&](int buf, int kt) {
        int k0 = kt << 4;
#pragma unroll
        for (int i = 0; i < 2; i++) {
            int c = tid + i * 256;
            int m = c >> 2, kc = c & 3;
            const float* src = A + (size_t)(mrow + m) * lda + k0 + kc * 4;
            bool p = (mrow + m < M) && (k0 + kc * 4 < Ka);
            cp16(&As[buf][m][kc * 4], src, p);
        }
#pragma unroll
        for (int i = 0; i < 2; i++) {
            int c = tid + i * 256;
            int n = c >> 2, kc = c & 3;
            const float* src = B + (size_t)(ncol + n) * ldb + k0 + kc * 4;
            bool p = (ncol + n < N) && (k0 + kc * 4 < Kb);
            cp16(&Bs[buf][n][kc * 4], src, p);
        }
    };

    load_tile(0, 0);
    asm volatile("cp.async.commit_group;\n" ::: "memory");

    for (int kt = 0; kt < NT; kt++) {
        int buf = kt & 1;
        if (kt + 1 < NT) {
            load_tile(buf ^ 1, kt + 1);
            asm volatile("cp.async.commit_group;\n" ::: "memory");
            asm volatile("cp.async.wait_group 1;\n" ::: "memory");
        } else {
            asm volatile("cp.async.wait_group 0;\n" ::: "memory");
        }
        __syncthreads();

#pragma unroll
        for (int ks = 0; ks < 16; ks += 8) {
            uint32_t afr[2][4], bfr[8][2];
#pragma unroll
            for (int mt = 0; mt < 2; mt++) {
                int r0 = warpM * 32 + mt * 16;
                afr[mt][0] = __float_as_uint(As[buf][r0 + g][ks + t]);
                afr[mt][1] = __float_as_uint(As[buf][r0 + g + 8][ks + t]);
                afr[mt][2] = __float_as_uint(As[buf][r0 + g][ks + t + 4]);
                afr[mt][3] = __float_as_uint(As[buf][r0 + g + 8][ks + t + 4]);
            }
#pragma unroll
            for (int nt = 0; nt < 8; nt++) {
                int c0 = warpN * 64 + nt * 8;
                bfr[nt][0] = __float_as_uint(Bs[buf][c0 + g][ks + t]);
                bfr[nt][1] = __float_as_uint(Bs[buf][c0 + g][ks + t + 4]);
            }
#pragma unroll
            for (int mt = 0; mt < 2; mt++)
#pragma unroll
                for (int nt = 0; nt < 8; nt++)
                    mma_tf32(acc[mt][nt], afr[mt], bfr[nt]);
        }
        __syncthreads();
    }

#pragma unroll
    for (int mt = 0; mt < 2; mt++) {
#pragma unroll
        for (int nt = 0; nt < 8; nt++) {
            int m0 = mrow + warpM * 32 + mt * 16 + g;
            int n0 = ncol + warpN * 64 + nt * 8 + 2 * t;
            if (n0 < N) {
                float b0 = bias[n0], b1 = bias[n0 + 1];
                if (m0 < M) {
                    C[(size_t)m0 * ldc + n0]     = acc[mt][nt][0] + b0;
                    C[(size_t)m0 * ldc + n0 + 1] = acc[mt][nt][1] + b1;
                }
                if (m0 + 8 < M) {
                    C[(size_t)(m0 + 8) * ldc + n0]     = acc[mt][nt][2] + b0;
                    C[(size_t)(m0 + 8) * ldc + n0 + 1] = acc[mt][nt][3] + b1;
                }
            }
        }
    }
}

// -------------------- persistent recurrence: 8-CTA cluster -------------------
// Each CTA owns 32 j-columns (128 gate cols). 8 warps: warp w -> local cols
// w*16..w*16+15, all 64 batch rows (4 m-frags). w_hh fragments in registers.
// Inter-step sync = cluster barrier (~380 cyc) instead of atomic spin.
__global__ void __launch_bounds__(256, 1) __cluster_dims__(RB, 1, 1)
k_rec(const float* __restrict__ w_hh) {
    extern __shared__ float sm[];
    float* hs   = sm;               // [64][260] h_prev
    float* gbuf = sm + 64 * 260;    // [64][132] gate exchange

    const int tid = threadIdx.x;
    const int lane = tid & 31;
    const int wid = tid >> 5;       // warpN 0..7
    const int g = lane >> 2;
    const int t = lane & 3;
    const int j0 = blockIdx.x * 32;

    // preload w_hh fragments (constant across steps): 128 regs
    uint32_t wb[2][32][2];
#pragma unroll
    for (int nt = 0; nt < 2; nt++) {
        int lc = wid * 16 + nt * 8 + g;                 // local col 0..127
        int wrow = (lc >> 5) * 256 + j0 + (lc & 31);    // gate*256 + j
        const float* wr = w_hh + (size_t)wrow * HH;
#pragma unroll
        for (int kt = 0; kt < 32; kt++) {
            wb[nt][kt][0] = f2tf(wr[kt * 8 + t]);
            wb[nt][kt][1] = f2tf(wr[kt * 8 + t + 4]);
        }
    }

    float creg[8];
#pragma unroll
    for (int q = 0; q < 8; q++) creg[q] = 0.f;
    const int cb = tid >> 2;          // cell batch row 0..63
    const int cj = (tid & 3) * 8;     // local j base 0..24

    for (int s = 0; s < SS; s++) {
        float acc[4][2][4];
#pragma unroll
        for (int mt = 0; mt < 4; mt++)
#pragma unroll
            for (int nt = 0; nt < 2; nt++)
#pragma unroll
                for (int q = 0; q < 4; q++) acc[mt][nt][q] = 0.f;

        if (s > 0) {
            const float4* src = (const float4*)(d_Hall + (size_t)(s - 1) * BB * HH);
#pragma unroll
            for (int i = 0; i < 16; i++) {
                int c = tid + i * 256;
                int m = c >> 6, kc = c & 63;
                *(float4*)&hs[m * 260 + kc * 4] = src[c];
            }
            __syncthreads();
#pragma unroll
            for (int kt = 0; kt < 32; kt++) {
                uint32_t af[4][4];
#pragma unroll
                for (int mt = 0; mt < 4; mt++) {
                    int r0 = mt * 16;
                    af[mt][0] = __float_as_uint(hs[(r0 + g) * 260 + kt * 8 + t]);
                    af[mt][1] = __float_as_uint(hs[(r0 + g + 8) * 260 + kt * 8 + t]);
                    af[mt][2] = __float_as_uint(hs[(r0 + g) * 260 + kt * 8 + t + 4]);
                    af[mt][3] = __float_as_uint(hs[(r0 + g + 8) * 260 + kt * 8 + t + 4]);
                }
#pragma unroll
                for (int mt = 0; mt < 4; mt++)
#pragma unroll
                    for (int nt = 0; nt < 2; nt++)
                        mma_tf32(acc[mt][nt], af[mt], wb[nt][kt]);
            }
        }

        // gates = acc + gpre -> gbuf
        const float* gp = d_gpre + (size_t)s * BB * GG;
#pragma unroll
        for (int mt = 0; mt < 4; mt++) {
#pragma unroll
            for (int nt = 0; nt < 2; nt++) {
                int b0r = mt * 16 + g;
                int lc0 = wid * 16 + nt * 8 + 2 * t;
                int r0 = (lc0 >> 5) * 256 + j0 + (lc0 & 31);
                float2 g0 = *(const float2*)&gp[(size_t)b0r * GG + r0];
                float2 g1 = *(const float2*)&gp[(size_t)(b0r + 8) * GG + r0];
                gbuf[b0r * 132 + lc0]           = acc[mt][nt][0] + g0.x;
                gbuf[b0r * 132 + lc0 + 1]       = acc[mt][nt][1] + g0.y;
                gbuf[(b0r + 8) * 132 + lc0]     = acc[mt][nt][2] + g1.x;
                gbuf[(b0r + 8) * 132 + lc0 + 1] = acc[mt][nt][3] + g1.y;
            }
        }
        __syncthreads();

        // LSTM cell: 8 cells per thread, store tf32-rounded h
        {
            const float* gb = gbuf + cb * 132;
            float hv[8];
#pragma unroll
            for (int q = 0; q < 8; q++) {
                int jj = cj + q;                         // 0..31 local j
                float gi = gb[jj], gf = gb[32 + jj];
                float gc = gb[64 + jj], go = gb[96 + jj];
                float ii = 1.f / (1.f + expf(-gi));
                float ff = 1.f / (1.f + expf(-gf));
                float gv = tanhf(gc);
                float oo = 1.f / (1.f + expf(-go));
                float cn = ff * creg[q] + ii * gv;
                creg[q] = cn;
                hv[q] = __uint_as_float(f2tf(oo * tanhf(cn)));
            }
            float* hd = d_Hall + ((size_t)s * BB + cb) * HH + j0 + cj;
            *(float4*)hd       = make_float4(hv[0], hv[1], hv[2], hv[3]);
            *(float4*)(hd + 4) = make_float4(hv[4], hv[5], hv[6], hv[7]);
        }

        if (s + 1 < SS) {
            __threadfence();
            asm volatile("barrier.cluster.arrive.aligned;" ::: "memory");
            asm volatile("barrier.cluster.wait.aligned;" ::: "memory");
        }
    }
}

// -------------------- output: t=0 one-hot plane ------------------------------
__global__ void k_fill(float* __restrict__ out) {
    int b = blockIdx.x;
    float* dst = out + (size_t)b * TT * VV;
    for (int v = threadIdx.x; v < VV; v += blockDim.x)
        dst[v] = (v == 1) ? 1.f : 0.f;
}

// -------------------- online log-softmax + transposed write ------------------
__global__ void __launch_bounds__(256) k_softmax(float* __restrict__ out) {
    const int r = blockIdx.x;
    const int s = r >> 6, b = r & 63;
    const int tid = threadIdx.x;
    const float4* src = (const float4*)(d_logits + (size_t)r * VV);

    float m = -1e30f, sum = 0.f;
    for (int c = tid; c < VV / 4; c += 256) {
        float4 x = src[c];
        float m4 = fmaxf(fmaxf(x.x, x.y), fmaxf(x.z, x.w));
        if (m4 > m) { sum *= expf(m - m4); m = m4; }
        sum += expf(x.x - m) + expf(x.y - m) + expf(x.z - m) + expf(x.w - m);
    }
#pragma unroll
    for (int o = 16; o; o >>= 1) {
        float mo = __shfl_xor_sync(0xffffffffu, m, o);
        float so = __shfl_xor_sync(0xffffffffu, sum, o);
        float M = fmaxf(m, mo);
        sum = sum * expf(m - M) + so * expf(mo - M);
        m = M;
    }
    __shared__ float sm_m[8], sm_s[8], s_lz;
    if ((tid & 31) == 0) { sm_m[tid >> 5] = m; sm_s[tid >> 5] = sum; }
    __syncthreads();
    if (tid == 0) {
        float M = sm_m[0], S = sm_s[0];
#pragma unroll
        for (int w = 1; w < 8; w++) {
            float mo = sm_m[w], so = sm_s[w];
            float MM = fmaxf(M, mo);
            S = S * expf(M - MM) + so * expf(mo - MM);
            M = MM;
        }
        s_lz = M + logf(S);
    }
    __syncthreads();
    float lz = s_lz;
    float4* dst = (float4*)(out + ((size_t)b * TT + s + 1) * VV);
    for (int c = tid; c < VV / 4; c += 256) {
        float4 x = src[c];
        x.x -= lz; x.y -= lz; x.z -= lz; x.w -= lz;
        dst[c] = x;
    }
}

// -------------------- launch ------------------------------------------------
extern "C" void kernel_launch(void* const* d_in, const int* in_sizes, int n_in,
                              void* d_out, int out_size) {
    const float* X    = (const float*)d_in[0];
    const float* emb  = (const float*)d_in[1];
    const float* fc1w = (const float*)d_in[2];
    const float* fc1b = (const float*)d_in[3];
    const float* wih  = (const float*)d_in[4];
    const float* whh  = (const float*)d_in[5];
    const float* bih  = (const float*)d_in[6];
    const float* bhh  = (const float*)d_in[7];
    const float* fc2w = (const float*)d_in[8];
    const float* fc2b = (const float*)d_in[9];
    const int*   lab  = (const int*)d_in[10];
    float* out = (float*)d_out;

    float *pAcat, *pBias2, *pGpre, *pHall, *pLogits;
    cudaGetSymbolAddress((void**)&pAcat,   d_Acat);
    cudaGetSymbolAddress((void**)&pBias2,  d_bias2);
    cudaGetSymbolAddress((void**)&pGpre,   d_gpre);
    cudaGetSymbolAddress((void**)&pHall,   d_Hall);
    cudaGetSymbolAddress((void**)&pLogits, d_logits);

    static int smem_set = 0;
    const int SMEMR = (64 * 260 + 64 * 132) * 4;   // 100352 B
    if (!smem_set) {
        cudaFuncSetAttribute(k_rec, cudaFuncAttributeMaxDynamicSharedMemorySize, SMEMR);
        smem_set = 1;
    }

    k_prep<<<1, 256>>>(lab, bih, bhh);
    k_fc1<<<dim3(8, 16), 256>>>(X, fc1w);
    k_fc1red<<<16, 256>>>(fc1b);
    k_buildA<<<(MROWS * AC4 + 255) / 256, 256>>>(emb);

    // gpre: [1984,1024] = Acat[1984,576] @ wih[1024,556]^T + (bih+bhh)
    k_tcgemm<<<dim3(8, 16), 256>>>(pAcat, KAP, wih, KIN, pBias2,
                                   pGpre, GG, MROWS, GG, KAP, KAP, KIN);

    // recurrence: 8-CTA cluster, persistent
    k_rec<<<RB, 256, SMEMR>>>(whh);

    // fc2: logits[1984,10000] = Hall @ fc2w^T + fc2b
    k_tcgemm<<<dim3(79, 16), 256>>>(pHall, HH, fc2w, HH, fc2b,
                                    pLogits, VV, MROWS, VV, HH, HH, HH);

    k_fill<<<64, 256>>>(out);
    k_softmax<<<MROWS, 256>>>(out);
}

// round 5
// speedup vs baseline: 1.8267x; 1.8267x over previous
#include <cuda_runtime.h>
#include <cuda_fp16.h>
#include <math.h>
#include <stdint.h>

// Problem dims
constexpr int BB = 64;
constexpr int TT = 32;
constexpr int SS = 31;     // scan steps (T-1)
constexpr int VV = 10000;
constexpr int EE = 300;
constexpr int HH = 256;
constexpr int FF = 4096;
constexpr int GG = 1024;   // 4*H
constexpr int KIN = HH + EE;   // 556
constexpr int KAP = 576;       // KIN padded to 32-multiple
constexpr int MROWS = SS * BB; // 1984

// -------------------- device scratch (static, no allocs) --------------------
__device__ float  d_Xp[BB * HH];
__device__ float  d_xpart[16 * BB * HH];
__device__ __half d_Acat[MROWS * KAP];     // [Xp | emb | 0] fp16
__device__ float  d_bias2[GG];             // b_ih + b_hh
__device__ float  d_gpre[MROWS * GG];      // precomputed gate inputs (fp32)
__device__ __half d_Hall[MROWS * HH];      // h history fp16 (fc2 A matrix)
__device__ float  d_logits[MROWS * VV];
__device__ int    d_labels[TT * BB];
__device__ __half d_w2h[VV * HH];          // fc2_w fp16
__device__ __half d_wihh[GG * KAP];        // w_ih fp16, K-padded
__device__ unsigned bar_cnt4[4];
__device__ volatile unsigned bar_gen4[4];

// -------------------- helpers ------------------------------------------------
__device__ __forceinline__ void cp16(void* smem_dst, const void* gsrc, bool pred) {
    uint32_t saddr = (uint32_t)__cvta_generic_to_shared(smem_dst);
    int sz = pred ? 16 : 0;
    asm volatile("cp.async.cg.shared.global [%0], [%1], 16, %2;\n"
                 :: "r"(saddr), "l"(gsrc), "r"(sz) : "memory");
}
__device__ __forceinline__ void mma_f16(float* d, const uint32_t* a, const uint32_t* b) {
    asm volatile(
        "mma.sync.aligned.m16n8k16.row.col.f32.f16.f16.f32 "
        "{%0,%1,%2,%3}, {%4,%5,%6,%7}, {%8,%9}, {%0,%1,%2,%3};"
        : "+f"(d[0]), "+f"(d[1]), "+f"(d[2]), "+f"(d[3])
        : "r"(a[0]), "r"(a[1]), "r"(a[2]), "r"(a[3]), "r"(b[0]), "r"(b[1]));
}

// -------------------- fused prep: label decode + combined bias ---------------
__global__ void k_prep(const int* __restrict__ lab,
                       const float* __restrict__ bih,
                       const float* __restrict__ bhh) {
    __shared__ int is64;
    if (threadIdx.x == 0) {
        int f = 1;
        for (int i = 1; i < 64 && f; i += 2)
            if (lab[i] != 0) f = 0;
        is64 = f;
    }
    __syncthreads();
    for (int i = threadIdx.x; i < TT * BB; i += blockDim.x)
        d_labels[i] = is64 ? (int)(((const long long*)lab)[i]) : lab[i];
    for (int i = threadIdx.x; i < GG; i += blockDim.x)
        d_bias2[i] = bih[i] + bhh[i];
}

// -------------------- fc1: Xp = X @ fc1_w.T + b (split-K SIMT) ---------------
__global__ void __launch_bounds__(256) k_fc1(const float* __restrict__ X,
                                             const float* __restrict__ W) {
    const int h0 = blockIdx.x * 32;
    const int kb = blockIdx.y;
    const int kbase = kb * 256;
    const int tid = threadIdx.x;
    __shared__ __align__(16) float Xs[32][68];
    __shared__ float Wsh[32][33];
    float acc[4][2];
#pragma unroll
    for (int q = 0; q < 4; q++) { acc[q][0] = 0.f; acc[q][1] = 0.f; }
    const int tb = (tid & 15) * 4;
    const int th = (tid >> 4) * 2;

    for (int t = 0; t < 8; t++) {
        int k0 = kbase + t * 32;
#pragma unroll
        for (int i = 0; i < 8; i++) {
            int idx = tid + i * 256;
            int b = idx >> 5, kk = idx & 31;
            Xs[kk][b] = X[(size_t)b * FF + k0 + kk];
        }
#pragma unroll
        for (int i = 0; i < 4; i++) {
            int idx = tid + i * 256;
            int hh = idx >> 5, kk = idx & 31;
            Wsh[kk][hh] = W[(size_t)(h0 + hh) * FF + k0 + kk];
        }
        __syncthreads();
#pragma unroll
        for (int kk = 0; kk < 32; kk++) {
            float4 x4 = *(const float4*)&Xs[kk][tb];
            float w0 = Wsh[kk][th], w1 = Wsh[kk][th + 1];
            acc[0][0] += x4.x * w0; acc[0][1] += x4.x * w1;
            acc[1][0] += x4.y * w0; acc[1][1] += x4.y * w1;
            acc[2][0] += x4.z * w0; acc[2][1] += x4.z * w1;
            acc[3][0] += x4.w * w0; acc[3][1] += x4.w * w1;
        }
        __syncthreads();
    }
#pragma unroll
    for (int q = 0; q < 4; q++)
#pragma unroll
        for (int j = 0; j < 2; j++)
            d_xpart[kb * (BB * HH) + (tb + q) * HH + h0 + th + j] = acc[q][j];
}

__global__ void k_fc1red(const float* __restrict__ fc1_b) {
    int i4 = blockIdx.x * 256 + threadIdx.x;
    if (i4 < BB * HH / 4) {
        const float4* bp = (const float4*)fc1_b;
        float4 s = bp[i4 & 63];
#pragma unroll
        for (int kb = 0; kb < 16; kb++) {
            float4 p = ((const float4*)(d_xpart + kb * BB * HH))[i4];
            s.x += p.x; s.y += p.y; s.z += p.z; s.w += p.w;
        }
        ((float4*)d_Xp)[i4] = s;
    }
}

// -------------------- build A = [Xp | emb | 0] (fp16) ------------------------
constexpr int AC4 = KAP / 4;   // 144 4-elem groups per row
__global__ void k_buildA(const float* __restrict__ emb_table) {
    int idx = blockIdx.x * 256 + threadIdx.x;
    if (idx >= MROWS * AC4) return;
    int r = idx / AC4, c = idx - r * AC4;
    int s = r >> 6, b = r & 63;
    float4 v;
    if (c < 64) {
        v = ((const float4*)d_Xp)[b * 64 + c];
    } else if (c < 139) {
        int tok = (s == 0) ? 1 : d_labels[s * BB + b];   // START_ID = 1
        v = *(const float4*)(emb_table + (size_t)tok * EE + (c - 64) * 4);
    } else {
        v = make_float4(0.f, 0.f, 0.f, 0.f);
    }
    __half2 p0 = __floats2half2_rn(v.x, v.y);
    __half2 p1 = __floats2half2_rn(v.z, v.w);
    uint2 u;
    u.x = *(uint32_t*)&p0;
    u.y = *(uint32_t*)&p1;
    ((uint2*)d_Acat)[idx] = u;
}

// -------------------- fp16 pre-conversion kernels ----------------------------
__global__ void k_cvt_fc2w(const float* __restrict__ w) {
    int idx = blockIdx.x * 256 + threadIdx.x;       // float4 units
    if (idx < VV * HH / 4) {
        float4 v = ((const float4*)w)[idx];
        __half2 p0 = __floats2half2_rn(v.x, v.y);
        __half2 p1 = __floats2half2_rn(v.z, v.w);
        uint2 u;
        u.x = *(uint32_t*)&p0;
        u.y = *(uint32_t*)&p1;
        ((uint2*)d_w2h)[idx] = u;
    }
}
__global__ void k_cvt_wih(const float* __restrict__ w) {
    int idx = blockIdx.x * 256 + threadIdx.x;
    if (idx < GG * KAP) {
        int r = idx / KAP, k = idx - r * KAP;
        d_wihh[idx] = (k < KIN) ? __float2half(w[r * KIN + k]) : __half(0.f);
    }
}

// -------------------- generic fp16 tensor-core GEMM --------------------------
// C[M,N] = A[M,K] @ B[N,K]^T + bias[N]; 128x128 tile, BK=32, 8 warps,
// m16n8k16 f16 with f32 accumulate. K must be a multiple of 32.
__global__ void __launch_bounds__(256) k_hgemm(
    const __half* __restrict__ A, int lda,
    const __half* __restrict__ B, int ldb,
    const float* __restrict__ bias,
    float* __restrict__ C, int ldc,
    int M, int N, int K)
{
    __shared__ __align__(16) __half As[2][128][40];
    __shared__ __align__(16) __half Bs[2][128][40];

    const int tid = threadIdx.x;
    const int lane = tid & 31;
    const int warpId = tid >> 5;
    const int warpM = warpId & 3;
    const int warpN = warpId >> 2;
    const int g = lane >> 2;
    const int t = lane & 3;

    const int ncol = blockIdx.x * 128;
    const int mrow = blockIdx.y * 128;

    float acc[2][8][4];
#pragma unroll
    for (int mt = 0; mt < 2; mt++)
#pragma unroll
        for (int nt = 0; nt < 8; nt++)
#pragma unroll
            for (int q = 0; q < 4; q++) acc[mt][nt][q] = 0.f;

    const int NT = K >> 5;

    auto load_tile = [&](int buf, int kt) {
        int k0 = kt << 5;
#pragma unroll
        for (int i = 0; i < 2; i++) {
            int c = tid + i * 256;
            int m = c >> 2, kc = (c & 3) * 8;
            cp16(&As[buf][m][kc], A + (size_t)(mrow + m) * lda + k0 + kc,
                 (mrow + m) < M);
        }
#pragma unroll
        for (int i = 0; i < 2; i++) {
            int c = tid + i * 256;
            int n = c >> 2, kc = (c & 3) * 8;
            cp16(&Bs[buf][n][kc], B + (size_t)(ncol + n) * ldb + k0 + kc,
                 (ncol + n) < N);
        }
    };

    load_tile(0, 0);
    asm volatile("cp.async.commit_group;\n" ::: "memory");

    for (int kt = 0; kt < NT; kt++) {
        int buf = kt & 1;
        if (kt + 1 < NT) {
            load_tile(buf ^ 1, kt + 1);
            asm volatile("cp.async.commit_group;\n" ::: "memory");
            asm volatile("cp.async.wait_group 1;\n" ::: "memory");
        } else {
            asm volatile("cp.async.wait_group 0;\n" ::: "memory");
        }
        __syncthreads();

#pragma unroll
        for (int ks = 0; ks < 32; ks += 16) {
            uint32_t afr[2][4], bfr[8][2];
#pragma unroll
            for (int mt = 0; mt < 2; mt++) {
                int r0 = warpM * 32 + mt * 16;
                afr[mt][0] = *(const uint32_t*)&As[buf][r0 + g][ks + 2 * t];
                afr[mt][1] = *(const uint32_t*)&As[buf][r0 + g + 8][ks + 2 * t];
                afr[mt][2] = *(const uint32_t*)&As[buf][r0 + g][ks + 2 * t + 8];
                afr[mt][3] = *(const uint32_t*)&As[buf][r0 + g + 8][ks + 2 * t + 8];
            }
#pragma unroll
            for (int nt = 0; nt < 8; nt++) {
                int c0 = warpN * 64 + nt * 8;
                bfr[nt][0] = *(const uint32_t*)&Bs[buf][c0 + g][ks + 2 * t];
                bfr[nt][1] = *(const uint32_t*)&Bs[buf][c0 + g][ks + 2 * t + 8];
            }
#pragma unroll
            for (int mt = 0; mt < 2; mt++)
#pragma unroll
                for (int nt = 0; nt < 8; nt++)
                    mma_f16(acc[mt][nt], afr[mt], bfr[nt]);
        }
        __syncthreads();
    }

#pragma unroll
    for (int mt = 0; mt < 2; mt++) {
#pragma unroll
        for (int nt = 0; nt < 8; nt++) {
            int m0 = mrow + warpM * 32 + mt * 16 + g;
            int n0 = ncol + warpN * 64 + nt * 8 + 2 * t;
            if (n0 < N) {
                float b0 = bias[n0], b1 = bias[n0 + 1];
                if (m0 < M) {
                    C[(size_t)m0 * ldc + n0]     = acc[mt][nt][0] + b0;
                    C[(size_t)m0 * ldc + n0 + 1] = acc[mt][nt][1] + b1;
                }
                if (m0 + 8 < M) {
                    C[(size_t)(m0 + 8) * ldc + n0]     = acc[mt][nt][2] + b0;
                    C[(size_t)(m0 + 8) * ldc + n0 + 1] = acc[mt][nt][3] + b1;
                }
            }
        }
    }
}

// -------------------- recurrence: 4 batch-groups x 16 j-blocks ---------------
// Batch rows are independent through the scan, so synchronization is only
// needed among the 16 j-blocks of one group (per-group atomic barrier).
// Block (grp, jb): batch rows grp*16..+15, j-cols jb*16..+15.
// 8 warps, each: m16 (all 16 rows) x n8 (8 of 64 gate-cols). w_hh in regs.
__global__ void __launch_bounds__(256, 1) k_rec(const float* __restrict__ w_hh) {
    __shared__ __align__(16) __half hs[16][264];   // h_prev (16 rows x 256)
    __shared__ float gbuf[16][68];                 // gate exchange

    const int tid = threadIdx.x;
    const int lane = tid & 31;
    const int wid = tid >> 5;
    const int g = lane >> 2;
    const int t = lane & 3;
    const int jb = blockIdx.x & 15;
    const int grp = blockIdx.x >> 4;
    const int j0 = jb * 16;
    const int brow0 = grp * 16;

    // preload w_hh fragments (fp16, 32 regs)
    uint32_t wb[16][2];
    {
        int lc = wid * 8 + g;                           // local col 0..63
        int wrow = (lc >> 4) * 256 + j0 + (lc & 15);    // gate*256 + j
        const float* wr = w_hh + (size_t)wrow * HH;
#pragma unroll
        for (int kt = 0; kt < 16; kt++) {
            __half2 h0 = __floats2half2_rn(wr[kt * 16 + 2 * t], wr[kt * 16 + 2 * t + 1]);
            __half2 h1 = __floats2half2_rn(wr[kt * 16 + 2 * t + 8], wr[kt * 16 + 2 * t + 9]);
            wb[kt][0] = *(uint32_t*)&h0;
            wb[kt][1] = *(uint32_t*)&h1;
        }
    }

    float creg = 0.f;
    const int cb = tid >> 4, cj = tid & 15;   // cell: 1 per thread
    const int lc = wid * 8 + 2 * t;
    const int r0 = (lc >> 4) * 256 + j0 + (lc & 15);
    unsigned mygen = bar_gen4[grp];

    for (int s = 0; s < SS; s++) {
        float acc[4] = {0.f, 0.f, 0.f, 0.f};

        // prefetch gpre (independent of h)
        const float* gp = d_gpre + ((size_t)s * BB + brow0) * GG;
        float2 g0 = *(const float2*)&gp[(size_t)g * GG + r0];
        float2 g1 = *(const float2*)&gp[(size_t)(g + 8) * GG + r0];

        if (s > 0) {
            const uint4* src = (const uint4*)(d_Hall + ((size_t)(s - 1) * BB + brow0) * HH);
#pragma unroll
            for (int i = 0; i < 2; i++) {
                int c = tid + i * 256;
                int m = c >> 5, kc = c & 31;
                *(uint4*)&hs[m][kc * 8] = src[m * 32 + kc];
            }
            __syncthreads();
#pragma unroll
            for (int kt = 0; kt < 16; kt++) {
                uint32_t af[4];
                af[0] = *(const uint32_t*)&hs[g][kt * 16 + 2 * t];
                af[1] = *(const uint32_t*)&hs[g + 8][kt * 16 + 2 * t];
                af[2] = *(const uint32_t*)&hs[g][kt * 16 + 2 * t + 8];
                af[3] = *(const uint32_t*)&hs[g + 8][kt * 16 + 2 * t + 8];
                mma_f16(acc, af, wb[kt]);
            }
        }

        gbuf[g][lc]         = acc[0] + g0.x;
        gbuf[g][lc + 1]     = acc[1] + g0.y;
        gbuf[g + 8][lc]     = acc[2] + g1.x;
        gbuf[g + 8][lc + 1] = acc[3] + g1.y;
        __syncthreads();

        {
            float gi = gbuf[cb][cj],      gf = gbuf[cb][16 + cj];
            float gc = gbuf[cb][32 + cj], go = gbuf[cb][48 + cj];
            float ii = 1.f / (1.f + expf(-gi));
            float ff = 1.f / (1.f + expf(-gf));
            float gv = tanhf(gc);
            float oo = 1.f / (1.f + expf(-go));
            float cn = ff * creg + ii * gv;
            creg = cn;
            d_Hall[((size_t)s * BB + brow0 + cb) * HH + j0 + cj] =
                __float2half(oo * tanhf(cn));
        }

        if (s + 1 < SS) {
            __threadfence();
            __syncthreads();
            if (tid == 0) {
                if (atomicInc(&bar_cnt4[grp], 15) == 15) {
                    bar_gen4[grp] = mygen + 1;
                } else {
                    while (bar_gen4[grp] == mygen) {}
                }
            }
            __syncthreads();
            mygen++;
        }
    }
}

// -------------------- fused one-hot fill + online log-softmax ----------------
__global__ void __launch_bounds__(256) k_softmax(float* __restrict__ out) {
    const int r = blockIdx.x;
    const int tid = threadIdx.x;
    if (r >= MROWS) {                      // one-hot t=0 plane
        int b = r - MROWS;
        float* dst = out + (size_t)b * TT * VV;
        for (int v = tid; v < VV; v += 256) dst[v] = (v == 1) ? 1.f : 0.f;
        return;
    }
    const int s = r >> 6, b = r & 63;
    const float4* src = (const float4*)(d_logits + (size_t)r * VV);

    float m = -1e30f, sum = 0.f;
    for (int c = tid; c < VV / 4; c += 256) {
        float4 x = src[c];
        float m4 = fmaxf(fmaxf(x.x, x.y), fmaxf(x.z, x.w));
        if (m4 > m) { sum *= expf(m - m4); m = m4; }
        sum += expf(x.x - m) + expf(x.y - m) + expf(x.z - m) + expf(x.w - m);
    }
#pragma unroll
    for (int o = 16; o; o >>= 1) {
        float mo = __shfl_xor_sync(0xffffffffu, m, o);
        float so = __shfl_xor_sync(0xffffffffu, sum, o);
        float M = fmaxf(m, mo);
        sum = sum * expf(m - M) + so * expf(mo - M);
        m = M;
    }
    __shared__ float sm_m[8], sm_s[8], s_lz;
    if ((tid & 31) == 0) { sm_m[tid >> 5] = m; sm_s[tid >> 5] = sum; }
    __syncthreads();
    if (tid == 0) {
        float M = sm_m[0], S = sm_s[0];
#pragma unroll
        for (int w = 1; w < 8; w++) {
            float mo = sm_m[w], so = sm_s[w];
            float MM = fmaxf(M, mo);
            S = S * expf(M - MM) + so * expf(mo - MM);
            M = MM;
        }
        s_lz = M + logf(S);
    }
    __syncthreads();
    float lz = s_lz;
    float4* dst = (float4*)(out + ((size_t)b * TT + s + 1) * VV);
    for (int c = tid; c < VV / 4; c += 256) {
        float4 x = src[c];
        x.x -= lz; x.y -= lz; x.z -= lz; x.w -= lz;
        dst[c] = x;
    }
}

// -------------------- launch ------------------------------------------------
extern "C" void kernel_launch(void* const* d_in, const int* in_sizes, int n_in,
                              void* d_out, int out_size) {
    const float* X    = (const float*)d_in[0];
    const float* emb  = (const float*)d_in[1];
    const float* fc1w = (const float*)d_in[2];
    const float* fc1b = (const float*)d_in[3];
    const float* wih  = (const float*)d_in[4];
    const float* whh  = (const float*)d_in[5];
    const float* bih  = (const float*)d_in[6];
    const float* bhh  = (const float*)d_in[7];
    const float* fc2w = (const float*)d_in[8];
    const float* fc2b = (const float*)d_in[9];
    const int*   lab  = (const int*)d_in[10];
    float* out = (float*)d_out;

    __half *pAcat, *pHall, *pW2h, *pWihh;
    float *pBias2, *pGpre, *pLogits;
    cudaGetSymbolAddress((void**)&pAcat,   d_Acat);
    cudaGetSymbolAddress((void**)&pBias2,  d_bias2);
    cudaGetSymbolAddress((void**)&pGpre,   d_gpre);
    cudaGetSymbolAddress((void**)&pHall,   d_Hall);
    cudaGetSymbolAddress((void**)&pLogits, d_logits);
    cudaGetSymbolAddress((void**)&pW2h,    d_w2h);
    cudaGetSymbolAddress((void**)&pWihh,   d_wihh);

    k_prep<<<1, 256>>>(lab, bih, bhh);
    k_fc1<<<dim3(8, 16), 256>>>(X, fc1w);
    k_fc1red<<<16, 256>>>(fc1b);
    k_buildA<<<(MROWS * AC4 + 255) / 256, 256>>>(emb);
    k_cvt_wih<<<(GG * KAP + 255) / 256, 256>>>(wih);
    k_cvt_fc2w<<<(VV * HH / 4 + 255) / 256, 256>>>(fc2w);

    // gpre: [1984,1024] = Acat[1984,576] @ wihh[1024,576]^T + (bih+bhh)
    k_hgemm<<<dim3(8, 16), 256>>>(pAcat, KAP, pWihh, KAP, pBias2,
                                  pGpre, GG, MROWS, GG, KAP);

    // recurrence: 64 blocks = 4 batch-groups x 16 j-blocks
    k_rec<<<64, 256>>>(whh);

    // fc2: logits[1984,10000] = Hall @ w2h^T + fc2b
    k_hgemm<<<dim3(79, 16), 256>>>(pHall, HH, pW2h, HH, fc2b,
                                   pLogits, VV, MROWS, VV, HH);

    k_softmax<<<MROWS + BB, 256>>>(out);
}